// round 2
// baseline (speedup 1.0000x reference)
#include <cuda_runtime.h>
#include <cstdint>

#define NN   20000
#define BB   32
#define DD   64
#define FF   2048      // D*B
#define OUTD 64
#define CHUNKS 4
#define CCOLS  512     // floats per column chunk (FF / CHUNKS)
#define EPB    8       // edges per block in spmm

// ---- scratch (device globals: allocation-free per harness rules) ----
__device__ __align__(16) float g_X0 [(size_t)NN * FF];
__device__ __align__(16) float g_Y1a[(size_t)NN * FF];
__device__ __align__(16) float g_Y2a[(size_t)NN * FF];
__device__ __align__(16) float g_Y1b[(size_t)NN * FF];
__device__ __align__(16) float g_Wc [5 * 64 * 64];
__device__ __align__(16) float g_Y2b[(size_t)NN * FF];

// ---------------------------------------------------------------------
// Zero the 4 accumulation buffers (one float4 per buffer per thread).
__global__ void k_zero_all() {
    size_t i = (size_t)blockIdx.x * blockDim.x + threadIdx.x;
    if (i < (size_t)NN * FF / 4) {
        float4 z = make_float4(0.f, 0.f, 0.f, 0.f);
        ((float4*)g_Y1a)[i] = z;
        ((float4*)g_Y2a)[i] = z;
        ((float4*)g_Y1b)[i] = z;
        ((float4*)g_Y2b)[i] = z;
    }
}

// ---------------------------------------------------------------------
// inputs [B, N, D] -> X0 [N, D*B] with X0[n][d*B + b] = inputs[b][n][d]
// One block per node, 512 threads.
__global__ void k_transpose(const float* __restrict__ inp) {
    __shared__ float s[64 * 33];
    int n   = blockIdx.x;
    int tid = threadIdx.x;
    int b = tid >> 4;          // 0..31
    int q = tid & 15;          // 0..15 (float4 index along D)
    float4 v = *(const float4*)(inp + ((size_t)b * NN + n) * DD + q * 4);
    s[(q * 4 + 0) * 33 + b] = v.x;
    s[(q * 4 + 1) * 33 + b] = v.y;
    s[(q * 4 + 2) * 33 + b] = v.z;
    s[(q * 4 + 3) * 33 + b] = v.w;
    __syncthreads();
    int j  = tid * 4;          // 0..2044
    int d  = j >> 5;
    int bb = j & 31;
    float4 o;
    o.x = s[d * 33 + bb + 0];
    o.y = s[d * 33 + bb + 1];
    o.z = s[d * 33 + bb + 2];
    o.w = s[d * 33 + bb + 3];
    *(float4*)(g_X0 + (size_t)n * FF + j) = o;
}

// ---------------------------------------------------------------------
// Combine weight: fold W[192:256] (s=3 duplicate of x0) into W[0:64].
// Wc layout: [5][64][64] matching feature order {X0, A0x, A0^2x, A1x, A1^2x}
__global__ void k_wcombine(const float* __restrict__ W) {
    int idx = blockIdx.x * blockDim.x + threadIdx.x;
    if (idx >= 5 * 64 * 64) return;
    int s   = idx >> 12;
    int rem = idx & 4095;
    int d   = rem >> 6;
    int o   = rem & 63;
    float val;
    if (s == 0)      val = W[d * 64 + o] + W[(192 + d) * 64 + o];
    else if (s == 1) val = W[( 64 + d) * 64 + o];
    else if (s == 2) val = W[(128 + d) * 64 + o];
    else if (s == 3) val = W[(256 + d) * 64 + o];
    else             val = W[(320 + d) * 64 + o];
    g_Wc[idx] = val;
}

// ---------------------------------------------------------------------
// SpMM: Y[r,:] += v * X[c,:], column-chunked so X-chunk + Y-chunk fit L2.
// grid.x = ceil(E/EPB), grid.y = chunk (y-major => chunk-major wave order).
// 256 threads: 128 col-lanes (float4) x 2 edge sublanes.
__global__ void k_spmm(const int* __restrict__ rows, const int* __restrict__ cols,
                       const float* __restrict__ vals, int E, int which) {
    const float* __restrict__ X;
    float* __restrict__ Y;
    if (which == 0)      { X = g_X0;  Y = g_Y1a; }
    else if (which == 1) { X = g_Y1a; Y = g_Y2a; }
    else if (which == 2) { X = g_X0;  Y = g_Y1b; }
    else                 { X = g_Y1b; Y = g_Y2b; }

    int chunk = blockIdx.y;
    int lane  = threadIdx.x & 127;
    int esub  = threadIdx.x >> 7;
    int coff  = chunk * CCOLS + lane * 4;
    int e0    = blockIdx.x * EPB;
    int eend  = min(e0 + EPB, E);
    for (int e = e0 + esub; e < eend; e += 2) {
        int   r = __ldg(rows + e);
        int   c = __ldg(cols + e);
        float v = __ldg(vals + e);
        float4 x = *(const float4*)(X + (size_t)c * FF + coff);
        float4 p = make_float4(x.x * v, x.y * v, x.z * v, x.w * v);
        float* dst = Y + (size_t)r * FF + coff;
        asm volatile("red.global.add.v4.f32 [%0], {%1,%2,%3,%4};"
                     :: "l"(dst), "f"(p.x), "f"(p.y), "f"(p.z), "f"(p.w)
                     : "memory");
    }
}

// ---------------------------------------------------------------------
// Output: out[b,n,o] = bias[o] + sum_s sum_d A_s[n][d*32+b] * Wc[s][d][o]
// One block per node, 128 threads, thread tile = 4 b x 4 o.
__global__ void k_out(const float* __restrict__ bias, float* __restrict__ out) {
    __shared__ float sA[5 * FF];   // 40 KB
    int n   = blockIdx.x;
    int tid = threadIdx.x;         // 128
    size_t base = (size_t)n * FF;
    {
        const float* srcs[5] = { g_X0 + base, g_Y1a + base, g_Y2a + base,
                                 g_Y1b + base, g_Y2b + base };
#pragma unroll
        for (int a = 0; a < 5; a++) {
            const float4* s4 = (const float4*)srcs[a];
            float4* d4 = (float4*)(sA + a * FF);
            for (int i = tid; i < FF / 4; i += 128)
                d4[i] = __ldg(s4 + i);
        }
    }
    __syncthreads();

    int bq = tid & 7;  int b0 = bq * 4;
    int oq = tid >> 3; int o0 = oq * 4;

    float acc[4][4];
    float4 bi = *(const float4*)(bias + o0);
#pragma unroll
    for (int i = 0; i < 4; i++) {
        acc[i][0] = bi.x; acc[i][1] = bi.y; acc[i][2] = bi.z; acc[i][3] = bi.w;
    }

#pragma unroll
    for (int s = 0; s < 5; s++) {
        const float* As = sA + s * FF;
        const float* Ws = g_Wc + s * 4096 + o0;
#pragma unroll 16
        for (int d = 0; d < 64; d++) {
            float4 a = *(const float4*)(As + d * 32 + b0);
            float4 w = __ldg((const float4*)(Ws + d * 64));
            acc[0][0] += a.x * w.x; acc[0][1] += a.x * w.y;
            acc[0][2] += a.x * w.z; acc[0][3] += a.x * w.w;
            acc[1][0] += a.y * w.x; acc[1][1] += a.y * w.y;
            acc[1][2] += a.y * w.z; acc[1][3] += a.y * w.w;
            acc[2][0] += a.z * w.x; acc[2][1] += a.z * w.y;
            acc[2][2] += a.z * w.z; acc[2][3] += a.z * w.w;
            acc[3][0] += a.w * w.x; acc[3][1] += a.w * w.y;
            acc[3][2] += a.w * w.z; acc[3][3] += a.w * w.w;
        }
    }

#pragma unroll
    for (int i = 0; i < 4; i++) {
        float4 r = make_float4(acc[i][0], acc[i][1], acc[i][2], acc[i][3]);
        *(float4*)(out + ((size_t)(b0 + i) * NN + n) * OUTD + o0) = r;
    }
}

// ---------------------------------------------------------------------
extern "C" void kernel_launch(void* const* d_in, const int* in_sizes, int n_in,
                              void* d_out, int out_size) {
    const float* inputs = (const float*)d_in[0];
    const int*   s0r    = (const int*)d_in[1];
    const int*   s0c    = (const int*)d_in[2];
    const float* s0v    = (const float*)d_in[3];
    const int*   s1r    = (const int*)d_in[4];
    const int*   s1c    = (const int*)d_in[5];
    const float* s1v    = (const float*)d_in[6];
    const float* W      = (const float*)d_in[7];
    const float* bias   = (const float*)d_in[8];
    float*       out    = (float*)d_out;
    int E = in_sizes[1];

    k_zero_all<<<40000, 256>>>();
    k_transpose<<<NN, 512>>>(inputs);
    k_wcombine<<<(5 * 64 * 64 + 255) / 256, 256>>>(W);

    dim3 sg((E + EPB - 1) / EPB, CHUNKS);
    k_spmm<<<sg, 256>>>(s0r, s0c, s0v, E, 0);   // X0  -> Y1a  (A0 x)
    k_spmm<<<sg, 256>>>(s0r, s0c, s0v, E, 1);   // Y1a -> Y2a  (A0^2 x)
    k_spmm<<<sg, 256>>>(s1r, s1c, s1v, E, 2);   // X0  -> Y1b  (A1 x)
    k_spmm<<<sg, 256>>>(s1r, s1c, s1v, E, 3);   // Y1b -> Y2b  (A1^2 x)

    k_out<<<NN, 128>>>(bias, out);
}

// round 5
// speedup vs baseline: 2.4541x; 2.4541x over previous
#include <cuda_runtime.h>
#include <cstdint>

#define NN    20000
#define BB    32
#define DD    64
#define FF    2048      // D*B
#define OUTD  64
#define CHUNKS 4
#define CCOLS  512      // floats per column chunk (FF / CHUNKS)
#define EMAX  640000

// ---- scratch (device globals: allocation-free per harness rules) ----
__device__ __align__(16) float g_X0 [(size_t)NN * FF];
__device__ __align__(16) float g_Y1a[(size_t)NN * FF];
__device__ __align__(16) float g_Y2a[(size_t)NN * FF];
__device__ __align__(16) float g_Y1b[(size_t)NN * FF];
__device__ __align__(16) float g_Y2b[(size_t)NN * FF];
__device__ __align__(16) float g_Wc [5 * 64 * 64];

__device__ int2 g_csr0[EMAX];
__device__ int2 g_csr1[EMAX];
__device__ int  g_cnt[2][NN];
__device__ int  g_off[2][NN + 1];
__device__ int  g_cur[2][NN];

// ---------------------------------------------------------------------
// f32x2 packed-FMA helpers (Blackwell FFMA2 — PTX-only path)
__device__ __forceinline__ unsigned long long fma2(unsigned long long a,
                                                   unsigned long long b,
                                                   unsigned long long c) {
    unsigned long long d;
    asm("fma.rn.f32x2 %0, %1, %2, %3;" : "=l"(d) : "l"(a), "l"(b), "l"(c));
    return d;
}
__device__ __forceinline__ unsigned long long pack2(float x, float y) {
    unsigned long long r;
    asm("mov.b64 %0, {%1, %2};" : "=l"(r) : "f"(x), "f"(y));
    return r;
}
__device__ __forceinline__ float2 unpack2(unsigned long long p) {
    float x, y;
    asm("mov.b64 {%0, %1}, %2;" : "=f"(x), "=f"(y) : "l"(p));
    return make_float2(x, y);
}

// ---------------------------------------------------------------------
// CSR build: zero counters, histogram rows, scan, scatter (col,val) pairs.
__global__ void k_czero() {
    int i = blockIdx.x * blockDim.x + threadIdx.x;
    if (i < 2 * NN) ((int*)g_cnt)[i] = 0;
}

__global__ void k_hist(const int* __restrict__ r0, const int* __restrict__ r1, int E) {
    int i = blockIdx.x * blockDim.x + threadIdx.x;
    if (i < E) {
        atomicAdd(&g_cnt[0][__ldg(r0 + i)], 1);
        atomicAdd(&g_cnt[1][__ldg(r1 + i)], 1);
    }
}

__global__ void k_scan() {
    __shared__ int part[1024];
    int tid = threadIdx.x;
    for (int s = 0; s < 2; s++) {
        int base = tid * 20;
        int loc[20];
        int sum = 0;
#pragma unroll
        for (int i = 0; i < 20; i++) {
            int idx = base + i;
            int c = (idx < NN) ? g_cnt[s][idx] : 0;
            loc[i] = sum;
            sum += c;
        }
        part[tid] = sum;
        __syncthreads();
        for (int o = 1; o < 1024; o <<= 1) {
            int v = (tid >= o) ? part[tid - o] : 0;
            __syncthreads();
            part[tid] += v;
            __syncthreads();
        }
        int pre = (tid > 0) ? part[tid - 1] : 0;
#pragma unroll
        for (int i = 0; i < 20; i++) {
            int idx = base + i;
            if (idx < NN) {
                int v = pre + loc[i];
                g_off[s][idx] = v;
                g_cur[s][idx] = v;
            }
        }
        if (tid == 1023) g_off[s][NN] = part[1023];
        __syncthreads();
    }
}

__global__ void k_scatter(const int* __restrict__ r0, const int* __restrict__ c0,
                          const float* __restrict__ v0,
                          const int* __restrict__ r1, const int* __restrict__ c1,
                          const float* __restrict__ v1, int E) {
    int i = blockIdx.x * blockDim.x + threadIdx.x;
    if (i >= E) return;
    {
        int p = atomicAdd(&g_cur[0][__ldg(r0 + i)], 1);
        g_csr0[p] = make_int2(__ldg(c0 + i), __float_as_int(__ldg(v0 + i)));
    }
    {
        int p = atomicAdd(&g_cur[1][__ldg(r1 + i)], 1);
        g_csr1[p] = make_int2(__ldg(c1 + i), __float_as_int(__ldg(v1 + i)));
    }
}

// ---------------------------------------------------------------------
// inputs [B, N, D] -> X0 [N, D*B] with X0[n][d*B + b] = inputs[b][n][d]
__global__ void k_transpose(const float* __restrict__ inp) {
    __shared__ float s[64 * 33];
    int n   = blockIdx.x;
    int tid = threadIdx.x;
    int b = tid >> 4;
    int q = tid & 15;
    float4 v = *(const float4*)(inp + ((size_t)b * NN + n) * DD + q * 4);
    s[(q * 4 + 0) * 33 + b] = v.x;
    s[(q * 4 + 1) * 33 + b] = v.y;
    s[(q * 4 + 2) * 33 + b] = v.z;
    s[(q * 4 + 3) * 33 + b] = v.w;
    __syncthreads();
    int j  = tid * 4;
    int d  = j >> 5;
    int bb = j & 31;
    float4 o;
    o.x = s[d * 33 + bb + 0];
    o.y = s[d * 33 + bb + 1];
    o.z = s[d * 33 + bb + 2];
    o.w = s[d * 33 + bb + 3];
    *(float4*)(g_X0 + (size_t)n * FF + j) = o;
}

// ---------------------------------------------------------------------
// Combine weight: fold W[192:256] (s=3 dup of x0) into W[0:64].
__global__ void k_wcombine(const float* __restrict__ W) {
    int idx = blockIdx.x * blockDim.x + threadIdx.x;
    if (idx >= 5 * 64 * 64) return;
    int s   = idx >> 12;
    int rem = idx & 4095;
    int d   = rem >> 6;
    int o   = rem & 63;
    float val;
    if (s == 0)      val = W[d * 64 + o] + W[(192 + d) * 64 + o];
    else if (s == 1) val = W[( 64 + d) * 64 + o];
    else if (s == 2) val = W[(128 + d) * 64 + o];
    else if (s == 3) val = W[(256 + d) * 64 + o];
    else             val = W[(320 + d) * 64 + o];
    g_Wc[idx] = val;
}

// ---------------------------------------------------------------------
// Row-gather SpMM: Y[r, chunk] = sum_{e in row r} v_e * X[c_e, chunk].
// No atomics, each output row written exactly once. Column-chunked so the
// X-chunk (41 MB) stays L2-resident; chunk advances in blockIdx.y (slowest).
__global__ void __launch_bounds__(128) k_gather(int which) {
    const int2* __restrict__ csr;
    const int*  __restrict__ off;
    const float* __restrict__ X;
    float* __restrict__ Y;
    if (which == 0)      { csr = g_csr0; off = g_off[0]; X = g_X0;  Y = g_Y1a; }
    else if (which == 1) { csr = g_csr0; off = g_off[0]; X = g_Y1a; Y = g_Y2a; }
    else if (which == 2) { csr = g_csr1; off = g_off[1]; X = g_X0;  Y = g_Y1b; }
    else                 { csr = g_csr1; off = g_off[1]; X = g_Y1b; Y = g_Y2b; }

    int r    = blockIdx.x;
    int coff = blockIdx.y * CCOLS + threadIdx.x * 4;
    int s = __ldg(off + r);
    int e = __ldg(off + r + 1);

    float4 acc0 = make_float4(0.f, 0.f, 0.f, 0.f);
    float4 acc1 = make_float4(0.f, 0.f, 0.f, 0.f);
    int i = s;
    for (; i + 1 < e; i += 2) {
        int2 cv0 = __ldg(csr + i);
        int2 cv1 = __ldg(csr + i + 1);
        float4 x0 = *(const float4*)(X + (size_t)cv0.x * FF + coff);
        float4 x1 = *(const float4*)(X + (size_t)cv1.x * FF + coff);
        float v0 = __int_as_float(cv0.y);
        float v1 = __int_as_float(cv1.y);
        acc0.x += v0 * x0.x; acc0.y += v0 * x0.y;
        acc0.z += v0 * x0.z; acc0.w += v0 * x0.w;
        acc1.x += v1 * x1.x; acc1.y += v1 * x1.y;
        acc1.z += v1 * x1.z; acc1.w += v1 * x1.w;
    }
    if (i < e) {
        int2 cv = __ldg(csr + i);
        float4 x = *(const float4*)(X + (size_t)cv.x * FF + coff);
        float v = __int_as_float(cv.y);
        acc0.x += v * x.x; acc0.y += v * x.y;
        acc0.z += v * x.z; acc0.w += v * x.w;
    }
    float4 out = make_float4(acc0.x + acc1.x, acc0.y + acc1.y,
                             acc0.z + acc1.z, acc0.w + acc1.w);
    *(float4*)(Y + (size_t)r * FF + coff) = out;
}

// ---------------------------------------------------------------------
// Output GEMM: out[b,n,o] = bias[o] + sum_s sum_d A_s[n][d*32+b] * Wc[s][d][o]
// One node per block, 128 threads, thread tile 4b x 4o, f32x2 packed FMAs.
__global__ void __launch_bounds__(128) k_out(const float* __restrict__ bias,
                                             float* __restrict__ out) {
    __shared__ float sA[5 * FF];   // 40 KB
    int n   = blockIdx.x;
    int tid = threadIdx.x;
    size_t base = (size_t)n * FF;
    {
        const float* srcs[5] = { g_X0 + base, g_Y1a + base, g_Y2a + base,
                                 g_Y1b + base, g_Y2b + base };
#pragma unroll
        for (int a = 0; a < 5; a++) {
            const float4* s4 = (const float4*)srcs[a];
            float4* d4 = (float4*)(sA + a * FF);
            for (int i = tid; i < FF / 4; i += 128)
                d4[i] = __ldg(s4 + i);
        }
    }
    __syncthreads();

    int bq = tid & 7;  int b0 = bq * 4;
    int oq = tid >> 3; int o0 = oq * 4;

    unsigned long long acc[4][2];
    {
        float4 bi = *(const float4*)(bias + o0);
        unsigned long long b01 = pack2(bi.x, bi.y);
        unsigned long long b23 = pack2(bi.z, bi.w);
#pragma unroll
        for (int i = 0; i < 4; i++) { acc[i][0] = b01; acc[i][1] = b23; }
    }

#pragma unroll
    for (int s = 0; s < 5; s++) {
        const float* As = sA + s * FF;
        const float* Ws = g_Wc + s * 4096 + o0;
#pragma unroll 8
        for (int d = 0; d < 64; d++) {
            float4 a = *(const float4*)(As + d * 32 + b0);
            float4 w = __ldg((const float4*)(Ws + d * 64));
            unsigned long long w01 = pack2(w.x, w.y);
            unsigned long long w23 = pack2(w.z, w.w);
            unsigned long long ax = pack2(a.x, a.x);
            unsigned long long ay = pack2(a.y, a.y);
            unsigned long long az = pack2(a.z, a.z);
            unsigned long long aw = pack2(a.w, a.w);
            acc[0][0] = fma2(ax, w01, acc[0][0]);
            acc[0][1] = fma2(ax, w23, acc[0][1]);
            acc[1][0] = fma2(ay, w01, acc[1][0]);
            acc[1][1] = fma2(ay, w23, acc[1][1]);
            acc[2][0] = fma2(az, w01, acc[2][0]);
            acc[2][1] = fma2(az, w23, acc[2][1]);
            acc[3][0] = fma2(aw, w01, acc[3][0]);
            acc[3][1] = fma2(aw, w23, acc[3][1]);
        }
    }

#pragma unroll
    for (int i = 0; i < 4; i++) {
        float2 lo = unpack2(acc[i][0]);
        float2 hi = unpack2(acc[i][1]);
        float4 r = make_float4(lo.x, lo.y, hi.x, hi.y);
        *(float4*)(out + ((size_t)(b0 + i) * NN + n) * OUTD + o0) = r;
    }
}

// ---------------------------------------------------------------------
extern "C" void kernel_launch(void* const* d_in, const int* in_sizes, int n_in,
                              void* d_out, int out_size) {
    const float* inputs = (const float*)d_in[0];
    const int*   s0r    = (const int*)d_in[1];
    const int*   s0c    = (const int*)d_in[2];
    const float* s0v    = (const float*)d_in[3];
    const int*   s1r    = (const int*)d_in[4];
    const int*   s1c    = (const int*)d_in[5];
    const float* s1v    = (const float*)d_in[6];
    const float* W      = (const float*)d_in[7];
    const float* bias   = (const float*)d_in[8];
    float*       out    = (float*)d_out;
    int E = in_sizes[1];

    // CSR build for both supports
    k_czero<<<(2 * NN + 255) / 256, 256>>>();
    k_hist<<<(E + 255) / 256, 256>>>(s0r, s1r, E);
    k_scan<<<1, 1024>>>();
    k_scatter<<<(E + 255) / 256, 256>>>(s0r, s0c, s0v, s1r, s1c, s1v, E);

    k_transpose<<<NN, 512>>>(inputs);
    k_wcombine<<<(5 * 64 * 64 + 255) / 256, 256>>>(W);

    dim3 sg(NN, CHUNKS);
    k_gather<<<sg, 128>>>(0);   // X0  -> Y1a  (A0 x)
    k_gather<<<sg, 128>>>(1);   // Y1a -> Y2a  (A0^2 x)
    k_gather<<<sg, 128>>>(2);   // X0  -> Y1b  (A1 x)
    k_gather<<<sg, 128>>>(3);   // Y1b -> Y2b  (A1^2 x)

    k_out<<<NN, 128>>>(bias, out);
}